// round 2
// baseline (speedup 1.0000x reference)
#include <cuda_runtime.h>
#include <cstdint>

// Problem constants (fixed by the reference)
#define N_TOKENS 131072
#define HIDDEN   2048
#define N_RANKS  8
#define N_EXPERTS 16
#define NSEG (N_RANKS * N_EXPERTS)   // 128
#define VEC_PER_ROW (HIDDEN / 4)     // 512 float4

// Scratch (no cudaMalloc allowed)
__device__ int g_in_start[NSEG];      // input segment start, flat order r*E + e
__device__ int g_out_start[NSEG + 1]; // output segment start, flat order e*R + r
__device__ int g_src_row[N_TOKENS];   // source row for each output row

// d_out float layout:
//   [0, N_TOKENS*HIDDEN)                  permute_tokens
//   [+0, +N_TOKENS)                       permute_per_token_scales
//   [+0, +N_TOKENS)                       idx (as float, exact: < 2^24)
//   [+0, +N_EXPERTS)                      expert_token_num (as float)
#define OFF_SCALES ((size_t)N_TOKENS * HIDDEN)
#define OFF_IDX    (OFF_SCALES + N_TOKENS)
#define OFF_ETN    (OFF_IDX + N_TOKENS)

// ---------------------------------------------------------------------------
// Kernel 1: segment offset tables + expert_token_num. One block, 128 threads.
// ---------------------------------------------------------------------------
__global__ void k_setup(const int* __restrict__ counts, float* __restrict__ out) {
    __shared__ int s_counts[NSEG];
    int t = threadIdx.x;
    if (t < NSEG) s_counts[t] = counts[t];
    __syncthreads();

    if (t == 0) {
        // input prefix (rank-major flat order == natural order)
        int acc = 0;
        for (int s = 0; s < NSEG; ++s) { g_in_start[s] = acc; acc += s_counts[s]; }
        // output prefix over expert-major order: seg s = e*R + r
        acc = 0;
        for (int s = 0; s < NSEG; ++s) {
            int e = s / N_RANKS;
            int r = s - e * N_RANKS;
            g_out_start[s] = acc;
            acc += s_counts[r * N_EXPERTS + e];
        }
        g_out_start[NSEG] = acc;
    }
    // expert_token_num[e] = sum_r counts[r][e]
    if (t < N_EXPERTS) {
        int sum = 0;
        #pragma unroll
        for (int r = 0; r < N_RANKS; ++r) sum += s_counts[r * N_EXPERTS + t];
        out[OFF_ETN + t] = (float)sum;
    }
}

// ---------------------------------------------------------------------------
// Kernel 2: per-token source index + permuted scales + idx output.
// ---------------------------------------------------------------------------
__global__ void k_index(const float* __restrict__ scales, float* __restrict__ out) {
    __shared__ int s_out_start[NSEG + 1];
    __shared__ int s_in_start[NSEG];
    for (int i = threadIdx.x; i < NSEG + 1; i += blockDim.x) s_out_start[i] = g_out_start[i];
    for (int i = threadIdx.x; i < NSEG;     i += blockDim.x) s_in_start[i]  = g_in_start[i];
    __syncthreads();

    int i = blockIdx.x * blockDim.x + threadIdx.x;
    if (i >= N_TOKENS) return;

    // binary search: largest s with out_start[s] <= i  (NSEG = 128 -> 7 steps)
    int lo = 0, hi = NSEG;
    #pragma unroll 7
    while (hi - lo > 1) {
        int mid = (lo + hi) >> 1;
        if (s_out_start[mid] <= i) lo = mid; else hi = mid;
    }
    int s = lo;                 // output segment: e*R + r
    int e = s / N_RANKS;
    int r = s - e * N_RANKS;
    int src = s_in_start[r * N_EXPERTS + e] + (i - s_out_start[s]);

    g_src_row[i]       = src;
    out[OFF_SCALES + i] = __ldg(&scales[src]);
    out[OFF_IDX + i]    = (float)src;
}

// ---------------------------------------------------------------------------
// Kernel 3: the big gather copy. One block per output row, float4 vectorized.
// 256 threads x 2 float4 = 512 float4 = 8 KB per row. Fully coalesced.
// ---------------------------------------------------------------------------
__global__ void __launch_bounds__(256, 8) k_copy(const float4* __restrict__ tokens,
                                                 float4* __restrict__ out) {
    int row = blockIdx.x;
    int src = __ldg(&g_src_row[row]);   // all 256 threads: same address, L1 broadcast

    const float4* __restrict__ in = tokens + (size_t)src * VEC_PER_ROW;
    float4* __restrict__ o        = out    + (size_t)row * VEC_PER_ROW;

    int t = threadIdx.x;
    float4 a = __ldg(&in[t]);
    float4 b = __ldg(&in[t + 256]);
    o[t]       = a;
    o[t + 256] = b;
}

// ---------------------------------------------------------------------------
extern "C" void kernel_launch(void* const* d_in, const int* in_sizes, int n_in,
                              void* d_out, int out_size) {
    const float* tokens = (const float*)d_in[0];
    const int*   counts = (const int*)d_in[1];     // [N_RANKS, N_EXPERTS]
    const float* scales = (const float*)d_in[2];
    // d_in[3] = expert_token_num_type (1), d_in[4] = idx_type (0) — fixed.
    float* out = (float*)d_out;

    k_setup<<<1, 128>>>(counts, out);
    k_index<<<(N_TOKENS + 255) / 256, 256>>>(scales, out);
    k_copy<<<N_TOKENS, 256>>>((const float4*)tokens, (float4*)out);
}